// round 8
// baseline (speedup 1.0000x reference)
#include <cuda_runtime.h>
#include <cuda_fp16.h>
#include <stdint.h>

#define BATCH 16384
#define NIN   128
#define NFEAT 8384
#define NOUT  512

#define BM 128
#define BN 128
#define BK 64
#define NCHUNK (NFEAT / BK)   // 131
#define THREADS 256
#define NSTAGE 3

// ---- global scratch (static __device__, no allocs) ----
__device__ __align__(16) __half g_A[(size_t)BATCH * NFEAT];    // expanded features fp16 (274.7MB)
__device__ __align__(16) __half g_Wt[(size_t)NOUT * NFEAT];    // W^T fp16 [n][k]
__device__ __align__(16) unsigned short g_tab[NFEAT];          // i | (j<<8); j=128 => linear

// ===================== prep kernels =====================

// transpose W [8384,512] f32 -> Wt [512,8384] fp16; blocks with y==0 also fill g_tab
__global__ void k_wt(const float* __restrict__ W) {
    __shared__ float sm[64][65];
    int k0 = blockIdx.x * 64, n0 = blockIdx.y * 64;
    int tid = threadIdx.x;

    if (blockIdx.y == 0 && tid < 64) {             // fold k_tab: f = k0 + tid covers 131*64 = 8384
        int f = k0 + tid;
        int i, j;
        if (f < NIN) { i = f; j = NIN; }
        else {
            int t = f - NIN;
            i = 0;
            while (NIN * (i + 1) - (i + 1) * i / 2 <= t) i++;
            j = i + (t - (NIN * i - i * (i - 1) / 2));
        }
        g_tab[f] = (unsigned short)(i | (j << 8));
    }

    for (int idx = tid; idx < 64 * 64; idx += 256) {
        int r = idx >> 6, c = idx & 63;           // r: k-local, c: n-local
        sm[c][r] = W[(size_t)(k0 + r) * NOUT + n0 + c];
    }
    __syncthreads();
    for (int idx = tid; idx < 64 * 32; idx += 256) {
        int nl = idx >> 5, kl = (idx & 31) * 2;
        float v0 = sm[nl][kl], v1 = sm[nl][kl + 1];
        uint32_t h;
        asm("cvt.rn.f16x2.f32 %0, %1, %2;" : "=r"(h) : "f"(v1), "f"(v0));
        size_t o = (size_t)(n0 + nl) * NFEAT + k0 + kl;   // even
        *(uint32_t*)((unsigned short*)g_Wt + o) = h;
    }
}

// expand X -> fp16 feature matrix [BATCH][NFEAT]
__global__ void __launch_bounds__(256, 4) k_expand(const float* __restrict__ X) {
    __shared__ float xs[129];
    const int b = blockIdx.x;
    const int tid = threadIdx.x;
    if (tid < 128) xs[tid] = X[(size_t)b * NIN + tid];
    if (tid == 0) xs[128] = 1.0f;
    __syncthreads();

    __half* A = g_A + (size_t)b * NFEAT;
    #pragma unroll 1
    for (int g = tid; g < NFEAT / 8; g += 256) {       // 1048 groups of 8 feats
        uint4 tv = *(const uint4*)&g_tab[g * 8];
        uint32_t tw[4] = {tv.x, tv.y, tv.z, tv.w};
        uint4 HP;
        uint32_t* hp = (uint32_t*)&HP;
        #pragma unroll
        for (int q = 0; q < 4; ++q) {
            uint32_t wv = tw[q];
            int i0 = wv & 255, j0 = (wv >> 8) & 255;
            int i1 = (wv >> 16) & 255, j1 = (wv >> 24) & 255;
            float v0 = xs[i0] * xs[j0];
            float v1 = xs[i1] * xs[j1];
            uint32_t h;
            asm("cvt.rn.f16x2.f32 %0, %1, %2;" : "=r"(h) : "f"(v1), "f"(v0));
            hp[q] = h;
        }
        *(uint4*)(A + g * 8) = HP;
    }
}

// ===================== PTX helpers =====================

__device__ __forceinline__ uint32_t smem_u32(const void* p) {
    uint32_t a;
    asm("{ .reg .u64 t; cvta.to.shared.u64 t, %1; cvt.u32.u64 %0, t; }" : "=r"(a) : "l"(p));
    return a;
}

__device__ __forceinline__ void ldsm4(uint32_t* r, uint32_t addr) {
    asm volatile("ldmatrix.sync.aligned.m8n8.x4.shared.b16 {%0,%1,%2,%3}, [%4];"
                 : "=r"(r[0]), "=r"(r[1]), "=r"(r[2]), "=r"(r[3]) : "r"(addr));
}

__device__ __forceinline__ void mma_f16(float* d, const uint32_t* a, const uint32_t* b) {
    asm volatile(
        "mma.sync.aligned.m16n8k16.row.col.f32.f16.f16.f32 "
        "{%0,%1,%2,%3}, {%4,%5,%6,%7}, {%8,%9}, {%0,%1,%2,%3};"
        : "+f"(d[0]), "+f"(d[1]), "+f"(d[2]), "+f"(d[3])
        : "r"(a[0]), "r"(a[1]), "r"(a[2]), "r"(a[3]), "r"(b[0]), "r"(b[1]));
}

__device__ __forceinline__ void cp16(uint32_t dst, const void* src) {
    asm volatile("cp.async.cg.shared.global [%0], [%1], 16;" :: "r"(dst), "l"(src) : "memory");
}

// ===================== main GEMM kernel =====================
// 8 warps, each owning a 32x64 output tile (4 warps/SMSP for latency hiding);
// register-double-buffered fragments + cross-chunk ks0 prefetch (tail barrier).
// SMEM per stage (32768 B): A 128x64 fp16 (16K) | B (+16384)
// Rows are 128B with SW128 XOR swizzle: chunk' = chunk ^ (row & 7)
#define STAGE_B 32768
#define SMEM_BYTES (NSTAGE * STAGE_B)   // 98304 -> 2 CTAs/SM

__global__ void __launch_bounds__(THREADS, 2)
k_main(const float* __restrict__ bias, float* __restrict__ out) {
    extern __shared__ char sm[];
    const uint32_t sb = smem_u32(sm);
    const int tid = threadIdx.x;
    const int lane = tid & 31;
    const int wid = tid >> 5;
    const int warp_m = wid & 3;       // 4 warps along M (32 rows each)
    const int warp_n = wid >> 2;      // 2 warps along N (64 cols each)
    const int n0 = blockIdx.x * BN;
    const int m0 = blockIdx.y * BM;

    float acc[2][8][4];
    #pragma unroll
    for (int a = 0; a < 2; ++a)
        #pragma unroll
        for (int b = 0; b < 8; ++b)
            #pragma unroll
            for (int c = 0; c < 4; ++c) acc[a][b][c] = 0.0f;

    // ---- cp.async staging: 1024 16B chunks each for A and B, 256 threads ----
    auto load_stage = [&](int s, int c) {
        const uint32_t base = sb + (uint32_t)(s * STAGE_B);
        const size_t koff = (size_t)c * BK;
        #pragma unroll
        for (int i = 0; i < 4; ++i) {
            int g = tid + i * 256;
            int r = g >> 3, ch = g & 7;
            uint32_t doff = (uint32_t)(r * 128 + (((ch ^ (r & 7))) << 4));
            cp16(base + doff,         g_A  + (size_t)(m0 + r) * NFEAT + koff + ch * 8);
            cp16(base + 16384 + doff, g_Wt + (size_t)(n0 + r) * NFEAT + koff + ch * 8);
        }
    };

    // ldmatrix per-lane constants
    const uint32_t sel = (uint32_t)(lane & 7);
    const uint32_t a_rowoff = (uint32_t)((warp_m * 32 + (lane & 15)) * 128);
    const uint32_t a_ch = (uint32_t)(lane >> 4);
    const uint32_t b_rowoff = (uint32_t)((warp_n * 64 + ((lane >> 4) << 3) + (lane & 7)) * 128);
    const uint32_t b_ch = (uint32_t)((lane >> 3) & 1);

    uint32_t Af[2][2][4], Bf[2][4][4];   // register double buffer

    auto load_frags = [&](uint32_t base, int ks, int buf) {
        const uint32_t ach = (((uint32_t)(ks * 2) + a_ch) ^ sel) << 4;
        const uint32_t bch = (((uint32_t)(ks * 2) + b_ch) ^ sel) << 4;
        #pragma unroll
        for (int mt = 0; mt < 2; ++mt)
            ldsm4(Af[buf][mt], base + a_rowoff + (uint32_t)(mt * 16 * 128) + ach);
        #pragma unroll
        for (int np = 0; np < 4; ++np)
            ldsm4(Bf[buf][np], base + 16384 + b_rowoff + (uint32_t)(np * 16 * 128) + bch);
    };

    auto mma_step = [&](int buf) {
        #pragma unroll
        for (int mt = 0; mt < 2; ++mt)
            #pragma unroll
            for (int np = 0; np < 4; ++np)
                #pragma unroll
                for (int h2 = 0; h2 < 2; ++h2)
                    mma_f16(acc[mt][np * 2 + h2], Af[buf][mt], &Bf[buf][np][h2 * 2]);
    };

    // ---- prologue ----
    load_stage(0, 0);
    asm volatile("cp.async.commit_group;" ::: "memory");
    load_stage(1, 1);
    asm volatile("cp.async.commit_group;" ::: "memory");
    asm volatile("cp.async.wait_group 1;" ::: "memory");  // G0 done -> stage 0 ready
    __syncthreads();
    load_frags(sb, 0, 0);                                 // chunk 0 ks0 -> buf0

    // ---- mainloop: barrier at tail; every chunk enters with ks0 in buf0 ----
    #pragma unroll 1
    for (int c = 0; c < NCHUNK; ++c) {
        if (c + 2 < NCHUNK) load_stage((c + 2) % 3, c + 2);
        asm volatile("cp.async.commit_group;" ::: "memory");  // empty commit near end keeps FIFO math valid
        const uint32_t base = sb + (uint32_t)((c % 3) * STAGE_B);
        load_frags(base, 1, 1); mma_step(0);
        load_frags(base, 2, 0); mma_step(1);
        load_frags(base, 3, 1); mma_step(0);
        // tail: ensure stage c+1 arrived (wait_group 1 -> G(c+1) retired) and visible
        asm volatile("cp.async.wait_group 1;" ::: "memory");
        __syncthreads();
        if (c + 1 < NCHUNK)
            load_frags(sb + (uint32_t)(((c + 1) % 3) * STAGE_B), 0, 0);  // next chunk ks0
        mma_step(1);                                       // hides the prefetch latency
    }

    // ---- epilogue ----
    const int gid = lane >> 2, tig = lane & 3;
    #pragma unroll
    for (int mt = 0; mt < 2; ++mt) {
        #pragma unroll
        for (int nt = 0; nt < 8; ++nt) {
            int row = m0 + warp_m * 32 + mt * 16 + gid;
            int col = n0 + warp_n * 64 + nt * 8 + tig * 2;
            float b0 = bias[col], b1 = bias[col + 1];
            float2 v0 = {acc[mt][nt][0] + b0, acc[mt][nt][1] + b1};
            float2 v1 = {acc[mt][nt][2] + b0, acc[mt][nt][3] + b1};
            *(float2*)(out + (size_t)row * NOUT + col) = v0;
            *(float2*)(out + (size_t)(row + 8) * NOUT + col) = v1;
        }
    }
}

// ===================== launcher =====================

extern "C" void kernel_launch(void* const* d_in, const int* in_sizes, int n_in,
                              void* d_out, int out_size) {
    const float* x = (const float*)d_in[0];
    const float* w = (const float*)d_in[1];
    const float* b = (const float*)d_in[2];
    float* out = (float*)d_out;

    cudaFuncSetAttribute(k_main, cudaFuncAttributeMaxDynamicSharedMemorySize, SMEM_BYTES);

    k_wt<<<dim3(NFEAT / 64, NOUT / 64), 256>>>(w);
    k_expand<<<BATCH, 256>>>(x);
    k_main<<<dim3(NOUT / BN, BATCH / BM), THREADS, SMEM_BYTES>>>(b, out);
}

// round 9
// speedup vs baseline: 1.0158x; 1.0158x over previous
#include <cuda_runtime.h>
#include <cuda_fp16.h>
#include <stdint.h>

#define BATCH 16384
#define NIN   128
#define NFEAT 8384
#define NOUT  512

#define BM 128
#define BN 128
#define BK 64
#define NCHUNK (NFEAT / BK)   // 131
#define THREADS 128
#define NSTAGE 3

// ---- global scratch (static __device__, no allocs) ----
__device__ __align__(16) __half g_A[(size_t)BATCH * NFEAT];    // expanded features fp16 (274.7MB)
__device__ __align__(16) __half g_Wt[(size_t)NOUT * NFEAT];    // W^T fp16 [n][k]

// ===================== prep kernels =====================

// transpose W [8384,512] f32 -> Wt [512,8384] fp16
__global__ void k_wt(const float* __restrict__ W) {
    __shared__ float sm[64][65];
    int k0 = blockIdx.x * 64, n0 = blockIdx.y * 64;
    int tid = threadIdx.x;
    for (int idx = tid; idx < 64 * 64; idx += 256) {
        int r = idx >> 6, c = idx & 63;           // r: k-local, c: n-local
        sm[c][r] = W[(size_t)(k0 + r) * NOUT + n0 + c];
    }
    __syncthreads();
    for (int idx = tid; idx < 64 * 32; idx += 256) {
        int nl = idx >> 5, kl = (idx & 31) * 2;
        float v0 = sm[nl][kl], v1 = sm[nl][kl + 1];
        uint32_t h;
        asm("cvt.rn.f16x2.f32 %0, %1, %2;" : "=r"(h) : "f"(v1), "f"(v0));
        size_t o = (size_t)(n0 + nl) * NFEAT + k0 + kl;   // even
        *(uint32_t*)((unsigned short*)g_Wt + o) = h;
    }
}

// expand X -> fp16 feature matrix [BATCH][NFEAT], row-contiguous scheme:
// features = [x (128) | rows i=0..127: x_i*x_j, j=i..127 (contiguous runs)]
__global__ void __launch_bounds__(256, 6) k_expand(const float* __restrict__ X) {
    __shared__ float xs[128];
    const int b = blockIdx.x;
    const int tid = threadIdx.x;
    if (tid < 128) xs[tid] = X[(size_t)b * NIN + tid];
    __syncthreads();

    __half* A = g_A + (size_t)b * NFEAT;

    // linear part: 128 halves = 64 half2 (offset 0 is 2-aligned)
    if (tid < 64) {
        __half2 h = __floats2half2_rn(xs[2 * tid], xs[2 * tid + 1]);
        *(__half2*)(A + 2 * tid) = h;
    }

    const int lane = tid & 31;
    const int w = tid >> 5;
    #pragma unroll 1
    for (int i = w; i < 128; i += 8) {
        const int L = 128 - i;                          // run length
        const int rs = 128 + 128 * i - (i * (i - 1)) / 2;  // run start
        const float xi = xs[i];
        const int h = rs & 1;                           // alignment head
        if (h && lane == 0)
            A[rs] = __float2half(xi * xs[i]);           // k = 0 (scalar)
        for (int k = h + 2 * lane; k + 1 < L; k += 64) {
            __half2 p = __floats2half2_rn(xi * xs[i + k], xi * xs[i + k + 1]);
            *(__half2*)(A + rs + k) = p;                // (rs+k) even -> aligned
        }
        if (((L - h) & 1) && lane == 0)
            A[rs + L - 1] = __float2half(xi * xs[i + L - 1]);  // tail (scalar)
    }
}

// ===================== PTX helpers =====================

__device__ __forceinline__ uint32_t smem_u32(const void* p) {
    uint32_t a;
    asm("{ .reg .u64 t; cvta.to.shared.u64 t, %1; cvt.u32.u64 %0, t; }" : "=r"(a) : "l"(p));
    return a;
}

__device__ __forceinline__ void ldsm4(uint32_t* r, uint32_t addr) {
    asm volatile("ldmatrix.sync.aligned.m8n8.x4.shared.b16 {%0,%1,%2,%3}, [%4];"
                 : "=r"(r[0]), "=r"(r[1]), "=r"(r[2]), "=r"(r[3]) : "r"(addr));
}

__device__ __forceinline__ void mma_f16(float* d, const uint32_t* a, const uint32_t* b) {
    asm volatile(
        "mma.sync.aligned.m16n8k16.row.col.f32.f16.f16.f32 "
        "{%0,%1,%2,%3}, {%4,%5,%6,%7}, {%8,%9}, {%0,%1,%2,%3};"
        : "+f"(d[0]), "+f"(d[1]), "+f"(d[2]), "+f"(d[3])
        : "r"(a[0]), "r"(a[1]), "r"(a[2]), "r"(a[3]), "r"(b[0]), "r"(b[1]));
}

__device__ __forceinline__ void cp16(uint32_t dst, const void* src) {
    asm volatile("cp.async.cg.shared.global [%0], [%1], 16;" :: "r"(dst), "l"(src) : "memory");
}

// ===================== main GEMM kernel (R7 — proven 341us) =====================
// 4 warps, each owning a 64x64 output tile; cross-chunk register pipelining:
// every chunk is entered with its ks0 fragments already loaded (no ldsm bubble).
// SMEM per stage (32768 B): A 128x64 fp16 (16K) | B (+16384)
// Rows are 128B with SW128 XOR swizzle: chunk' = chunk ^ (row & 7)
#define STAGE_B 32768
#define SMEM_BYTES (NSTAGE * STAGE_B)   // 98304 -> 2 CTAs/SM

__global__ void __launch_bounds__(THREADS, 2)
k_main(const float* __restrict__ bias, float* __restrict__ out) {
    extern __shared__ char sm[];
    const uint32_t sb = smem_u32(sm);
    const int tid = threadIdx.x;
    const int lane = tid & 31;
    const int wid = tid >> 5;
    const int warp_m = wid & 1;       // 2 warps along M (64 rows each)
    const int warp_n = wid >> 1;      // 2 warps along N (64 cols each)
    const int n0 = blockIdx.x * BN;
    const int m0 = blockIdx.y * BM;

    float acc[4][8][4];
    #pragma unroll
    for (int a = 0; a < 4; ++a)
        #pragma unroll
        for (int b = 0; b < 8; ++b)
            #pragma unroll
            for (int c = 0; c < 4; ++c) acc[a][b][c] = 0.0f;

    // ---- cp.async staging: 1024 16B chunks each for A and B, 128 threads ----
    auto load_stage = [&](int s, int c) {
        const uint32_t base = sb + (uint32_t)(s * STAGE_B);
        const size_t koff = (size_t)c * BK;
        #pragma unroll
        for (int i = 0; i < 8; ++i) {
            int g = tid + i * 128;
            int r = g >> 3, ch = g & 7;
            uint32_t doff = (uint32_t)(r * 128 + (((ch ^ (r & 7))) << 4));
            cp16(base + doff,         g_A  + (size_t)(m0 + r) * NFEAT + koff + ch * 8);
            cp16(base + 16384 + doff, g_Wt + (size_t)(n0 + r) * NFEAT + koff + ch * 8);
        }
    };

    // ldmatrix per-lane constants
    const uint32_t sel = (uint32_t)(lane & 7);
    const uint32_t a_rowoff = (uint32_t)((warp_m * 64 + (lane & 15)) * 128);
    const uint32_t a_ch = (uint32_t)(lane >> 4);
    const uint32_t b_rowoff = (uint32_t)((warp_n * 64 + ((lane >> 4) << 3) + (lane & 7)) * 128);
    const uint32_t b_ch = (uint32_t)((lane >> 3) & 1);

    uint32_t Af[2][4][4], Bf[2][4][4];   // register double buffer

    auto load_frags = [&](uint32_t base, int ks, int buf) {
        const uint32_t ach = (((uint32_t)(ks * 2) + a_ch) ^ sel) << 4;
        const uint32_t bch = (((uint32_t)(ks * 2) + b_ch) ^ sel) << 4;
        #pragma unroll
        for (int mt = 0; mt < 4; ++mt)
            ldsm4(Af[buf][mt], base + a_rowoff + (uint32_t)(mt * 16 * 128) + ach);
        #pragma unroll
        for (int np = 0; np < 4; ++np)
            ldsm4(Bf[buf][np], base + 16384 + b_rowoff + (uint32_t)(np * 16 * 128) + bch);
    };

    auto mma_step = [&](int buf) {
        #pragma unroll
        for (int mt = 0; mt < 4; ++mt)
            #pragma unroll
            for (int np = 0; np < 4; ++np)
                #pragma unroll
                for (int h2 = 0; h2 < 2; ++h2)
                    mma_f16(acc[mt][np * 2 + h2], Af[buf][mt], &Bf[buf][np][h2 * 2]);
    };

    // ---- prologue ----
    load_stage(0, 0);
    asm volatile("cp.async.commit_group;" ::: "memory");
    load_stage(1, 1);
    asm volatile("cp.async.commit_group;" ::: "memory");
    asm volatile("cp.async.wait_group 1;" ::: "memory");  // G0 done -> stage 0 ready
    __syncthreads();
    load_frags(sb, 0, 0);                                 // chunk 0 ks0 -> buf0

    // ---- mainloop: barrier at tail; every chunk enters with ks0 in buf0 ----
    #pragma unroll 1
    for (int c = 0; c < NCHUNK; ++c) {
        if (c + 2 < NCHUNK) load_stage((c + 2) % 3, c + 2);
        asm volatile("cp.async.commit_group;" ::: "memory");  // empty commit near end keeps FIFO math valid
        const uint32_t base = sb + (uint32_t)((c % 3) * STAGE_B);
        load_frags(base, 1, 1); mma_step(0);
        load_frags(base, 2, 0); mma_step(1);
        load_frags(base, 3, 1); mma_step(0);
        // tail: ensure stage c+1 arrived (wait_group 1 -> G(c+1) retired) and visible
        asm volatile("cp.async.wait_group 1;" ::: "memory");
        __syncthreads();
        if (c + 1 < NCHUNK)
            load_frags(sb + (uint32_t)(((c + 1) % 3) * STAGE_B), 0, 0);  // next chunk ks0
        mma_step(1);                                       // hides the prefetch latency
    }

    // ---- epilogue ----
    const int gid = lane >> 2, tig = lane & 3;
    #pragma unroll
    for (int mt = 0; mt < 4; ++mt) {
        #pragma unroll
        for (int nt = 0; nt < 8; ++nt) {
            int row = m0 + warp_m * 64 + mt * 16 + gid;
            int col = n0 + warp_n * 64 + nt * 8 + tig * 2;
            float b0 = bias[col], b1 = bias[col + 1];
            float2 v0 = {acc[mt][nt][0] + b0, acc[mt][nt][1] + b1};
            float2 v1 = {acc[mt][nt][2] + b0, acc[mt][nt][3] + b1};
            *(float2*)(out + (size_t)row * NOUT + col) = v0;
            *(float2*)(out + (size_t)(row + 8) * NOUT + col) = v1;
        }
    }
}

// ===================== launcher =====================

extern "C" void kernel_launch(void* const* d_in, const int* in_sizes, int n_in,
                              void* d_out, int out_size) {
    const float* x = (const float*)d_in[0];
    const float* w = (const float*)d_in[1];
    const float* b = (const float*)d_in[2];
    float* out = (float*)d_out;

    cudaFuncSetAttribute(k_main, cudaFuncAttributeMaxDynamicSharedMemorySize, SMEM_BYTES);

    k_wt<<<dim3(NFEAT / 64, NOUT / 64), 256>>>(w);
    k_expand<<<BATCH, 256>>>(x);
    k_main<<<dim3(NOUT / BN, BATCH / BM), THREADS, SMEM_BYTES>>>(b, out);
}

// round 10
// speedup vs baseline: 1.1367x; 1.1190x over previous
#include <cuda_runtime.h>
#include <cuda_fp16.h>
#include <stdint.h>

#define BATCH 16384
#define NIN   128
#define NFEAT 8384
#define NOUT  512

#define BM 128
#define BN 128
#define BK 64
#define NCHUNK (NFEAT / BK)   // 131
#define THREADS 128
#define NSTAGE 3

// ---- global scratch (static __device__, no allocs) ----
__device__ __align__(16) __half g_A[(size_t)BATCH * NFEAT];    // expanded features fp16 (274.7MB)
__device__ __align__(16) __half g_Wt[(size_t)NOUT * NFEAT];    // W^T fp16 [n][k]
__device__ __align__(16) unsigned short g_tab[NFEAT];          // i | (j<<8); j=128 => linear

// ===================== prep kernels =====================

// transpose W [8384,512] f32 -> Wt [512,8384] fp16; blocks with y==0 also fill g_tab
__global__ void k_wt(const float* __restrict__ W) {
    __shared__ float sm[64][65];
    int k0 = blockIdx.x * 64, n0 = blockIdx.y * 64;
    int tid = threadIdx.x;

    if (blockIdx.y == 0 && tid < 64) {             // f = k0 + tid covers 131*64 = 8384
        int f = k0 + tid;
        int i, j;
        if (f < NIN) { i = f; j = NIN; }
        else {
            int t = f - NIN;
            i = 0;
            while (NIN * (i + 1) - (i + 1) * i / 2 <= t) i++;
            j = i + (t - (NIN * i - i * (i - 1) / 2));
        }
        g_tab[f] = (unsigned short)(i | (j << 8));
    }

    for (int idx = tid; idx < 64 * 64; idx += 256) {
        int r = idx >> 6, c = idx & 63;           // r: k-local, c: n-local
        sm[c][r] = W[(size_t)(k0 + r) * NOUT + n0 + c];
    }
    __syncthreads();
    for (int idx = tid; idx < 64 * 32; idx += 256) {
        int nl = idx >> 5, kl = (idx & 31) * 2;
        float v0 = sm[nl][kl], v1 = sm[nl][kl + 1];
        uint32_t h;
        asm("cvt.rn.f16x2.f32 %0, %1, %2;" : "=r"(h) : "f"(v1), "f"(v0));
        size_t o = (size_t)(n0 + nl) * NFEAT + k0 + kl;   // even
        *(uint32_t*)((unsigned short*)g_Wt + o) = h;
    }
}

// expand X -> fp16 feature matrix [BATCH][NFEAT]
// Table-driven with uniform-i fast path (8 consecutive j -> sequential LDS).
__global__ void __launch_bounds__(256, 4) k_expand(const float* __restrict__ X) {
    __shared__ float xs[129];
    const int b = blockIdx.x;
    const int tid = threadIdx.x;
    if (tid < 128) xs[tid] = X[(size_t)b * NIN + tid];
    if (tid == 0) xs[128] = 1.0f;
    __syncthreads();

    __half* A = g_A + (size_t)b * NFEAT;
    #pragma unroll 1
    for (int g = tid; g < NFEAT / 8; g += 256) {       // 1048 groups of 8 feats
        uint4 tv = *(const uint4*)&g_tab[g * 8];
        uint4 HP;
        uint32_t* hp = (uint32_t*)&HP;

        const uint32_t lomask = 0x00FF00FFu;
        uint32_t i0 = tv.x & 255u;
        uint32_t rep = i0 * 0x00010001u;
        bool uni = ((tv.x & lomask) == rep) && ((tv.y & lomask) == rep) &&
                   ((tv.z & lomask) == rep) && ((tv.w & lomask) == rep);

        if (uni) {                                  // one run: i fixed, j consecutive
            const float xi = xs[i0];
            const int j0 = (int)((tv.x >> 8) & 255u);
            #pragma unroll
            for (int q = 0; q < 4; ++q) {
                float v0 = xi * xs[j0 + 2 * q];
                float v1 = xi * xs[j0 + 2 * q + 1];
                asm("cvt.rn.f16x2.f32 %0, %1, %2;" : "=r"(hp[q]) : "f"(v1), "f"(v0));
            }
        } else {                                    // boundary / linear groups
            uint32_t tw[4] = {tv.x, tv.y, tv.z, tv.w};
            #pragma unroll
            for (int q = 0; q < 4; ++q) {
                uint32_t wv = tw[q];
                int ia = wv & 255, ja = (wv >> 8) & 255;
                int ib = (wv >> 16) & 255, jb = (wv >> 24) & 255;
                float v0 = xs[ia] * xs[ja];
                float v1 = xs[ib] * xs[jb];
                asm("cvt.rn.f16x2.f32 %0, %1, %2;" : "=r"(hp[q]) : "f"(v1), "f"(v0));
            }
        }
        *(uint4*)(A + g * 8) = HP;
    }
}

// ===================== PTX helpers =====================

__device__ __forceinline__ uint32_t smem_u32(const void* p) {
    uint32_t a;
    asm("{ .reg .u64 t; cvta.to.shared.u64 t, %1; cvt.u32.u64 %0, t; }" : "=r"(a) : "l"(p));
    return a;
}

__device__ __forceinline__ void ldsm4(uint32_t* r, uint32_t addr) {
    asm volatile("ldmatrix.sync.aligned.m8n8.x4.shared.b16 {%0,%1,%2,%3}, [%4];"
                 : "=r"(r[0]), "=r"(r[1]), "=r"(r[2]), "=r"(r[3]) : "r"(addr));
}

__device__ __forceinline__ void mma_f16(float* d, const uint32_t* a, const uint32_t* b) {
    asm volatile(
        "mma.sync.aligned.m16n8k16.row.col.f32.f16.f16.f32 "
        "{%0,%1,%2,%3}, {%4,%5,%6,%7}, {%8,%9}, {%0,%1,%2,%3};"
        : "+f"(d[0]), "+f"(d[1]), "+f"(d[2]), "+f"(d[3])
        : "r"(a[0]), "r"(a[1]), "r"(a[2]), "r"(a[3]), "r"(b[0]), "r"(b[1]));
}

__device__ __forceinline__ void cp16(uint32_t dst, const void* src) {
    asm volatile("cp.async.cg.shared.global [%0], [%1], 16;" :: "r"(dst), "l"(src) : "memory");
}

// ===================== main GEMM kernel (R7 — proven 341us) =====================
// 4 warps, each owning a 64x64 output tile; cross-chunk register pipelining:
// every chunk is entered with its ks0 fragments already loaded (no ldsm bubble).
// SMEM per stage (32768 B): A 128x64 fp16 (16K) | B (+16384)
// Rows are 128B with SW128 XOR swizzle: chunk' = chunk ^ (row & 7)
#define STAGE_B 32768
#define SMEM_BYTES (NSTAGE * STAGE_B)   // 98304 -> 2 CTAs/SM

__global__ void __launch_bounds__(THREADS, 2)
k_main(const float* __restrict__ bias, float* __restrict__ out) {
    extern __shared__ char sm[];
    const uint32_t sb = smem_u32(sm);
    const int tid = threadIdx.x;
    const int lane = tid & 31;
    const int wid = tid >> 5;
    const int warp_m = wid & 1;       // 2 warps along M (64 rows each)
    const int warp_n = wid >> 1;      // 2 warps along N (64 cols each)
    const int n0 = blockIdx.x * BN;
    const int m0 = blockIdx.y * BM;

    float acc[4][8][4];
    #pragma unroll
    for (int a = 0; a < 4; ++a)
        #pragma unroll
        for (int b = 0; b < 8; ++b)
            #pragma unroll
            for (int c = 0; c < 4; ++c) acc[a][b][c] = 0.0f;

    // ---- cp.async staging: 1024 16B chunks each for A and B, 128 threads ----
    auto load_stage = [&](int s, int c) {
        const uint32_t base = sb + (uint32_t)(s * STAGE_B);
        const size_t koff = (size_t)c * BK;
        #pragma unroll
        for (int i = 0; i < 8; ++i) {
            int g = tid + i * 128;
            int r = g >> 3, ch = g & 7;
            uint32_t doff = (uint32_t)(r * 128 + (((ch ^ (r & 7))) << 4));
            cp16(base + doff,         g_A  + (size_t)(m0 + r) * NFEAT + koff + ch * 8);
            cp16(base + 16384 + doff, g_Wt + (size_t)(n0 + r) * NFEAT + koff + ch * 8);
        }
    };

    // ldmatrix per-lane constants
    const uint32_t sel = (uint32_t)(lane & 7);
    const uint32_t a_rowoff = (uint32_t)((warp_m * 64 + (lane & 15)) * 128);
    const uint32_t a_ch = (uint32_t)(lane >> 4);
    const uint32_t b_rowoff = (uint32_t)((warp_n * 64 + ((lane >> 4) << 3) + (lane & 7)) * 128);
    const uint32_t b_ch = (uint32_t)((lane >> 3) & 1);

    uint32_t Af[2][4][4], Bf[2][4][4];   // register double buffer

    auto load_frags = [&](uint32_t base, int ks, int buf) {
        const uint32_t ach = (((uint32_t)(ks * 2) + a_ch) ^ sel) << 4;
        const uint32_t bch = (((uint32_t)(ks * 2) + b_ch) ^ sel) << 4;
        #pragma unroll
        for (int mt = 0; mt < 4; ++mt)
            ldsm4(Af[buf][mt], base + a_rowoff + (uint32_t)(mt * 16 * 128) + ach);
        #pragma unroll
        for (int np = 0; np < 4; ++np)
            ldsm4(Bf[buf][np], base + 16384 + b_rowoff + (uint32_t)(np * 16 * 128) + bch);
    };

    auto mma_step = [&](int buf) {
        #pragma unroll
        for (int mt = 0; mt < 4; ++mt)
            #pragma unroll
            for (int np = 0; np < 4; ++np)
                #pragma unroll
                for (int h2 = 0; h2 < 2; ++h2)
                    mma_f16(acc[mt][np * 2 + h2], Af[buf][mt], &Bf[buf][np][h2 * 2]);
    };

    // ---- prologue ----
    load_stage(0, 0);
    asm volatile("cp.async.commit_group;" ::: "memory");
    load_stage(1, 1);
    asm volatile("cp.async.commit_group;" ::: "memory");
    asm volatile("cp.async.wait_group 1;" ::: "memory");  // G0 done -> stage 0 ready
    __syncthreads();
    load_frags(sb, 0, 0);                                 // chunk 0 ks0 -> buf0

    // ---- mainloop: barrier at tail; every chunk enters with ks0 in buf0 ----
    #pragma unroll 1
    for (int c = 0; c < NCHUNK; ++c) {
        if (c + 2 < NCHUNK) load_stage((c + 2) % 3, c + 2);
        asm volatile("cp.async.commit_group;" ::: "memory");  // empty commit near end keeps FIFO math valid
        const uint32_t base = sb + (uint32_t)((c % 3) * STAGE_B);
        load_frags(base, 1, 1); mma_step(0);
        load_frags(base, 2, 0); mma_step(1);
        load_frags(base, 3, 1); mma_step(0);
        // tail: ensure stage c+1 arrived (wait_group 1 -> G(c+1) retired) and visible
        asm volatile("cp.async.wait_group 1;" ::: "memory");
        __syncthreads();
        if (c + 1 < NCHUNK)
            load_frags(sb + (uint32_t)(((c + 1) % 3) * STAGE_B), 0, 0);  // next chunk ks0
        mma_step(1);                                       // hides the prefetch latency
    }

    // ---- epilogue ----
    const int gid = lane >> 2, tig = lane & 3;
    #pragma unroll
    for (int mt = 0; mt < 4; ++mt) {
        #pragma unroll
        for (int nt = 0; nt < 8; ++nt) {
            int row = m0 + warp_m * 64 + mt * 16 + gid;
            int col = n0 + warp_n * 64 + nt * 8 + tig * 2;
            float b0 = bias[col], b1 = bias[col + 1];
            float2 v0 = {acc[mt][nt][0] + b0, acc[mt][nt][1] + b1};
            float2 v1 = {acc[mt][nt][2] + b0, acc[mt][nt][3] + b1};
            *(float2*)(out + (size_t)row * NOUT + col) = v0;
            *(float2*)(out + (size_t)(row + 8) * NOUT + col) = v1;
        }
    }
}

// ===================== launcher =====================

extern "C" void kernel_launch(void* const* d_in, const int* in_sizes, int n_in,
                              void* d_out, int out_size) {
    const float* x = (const float*)d_in[0];
    const float* w = (const float*)d_in[1];
    const float* b = (const float*)d_in[2];
    float* out = (float*)d_out;

    cudaFuncSetAttribute(k_main, cudaFuncAttributeMaxDynamicSharedMemorySize, SMEM_BYTES);

    k_wt<<<dim3(NFEAT / 64, NOUT / 64), 256>>>(w);
    k_expand<<<BATCH, 256>>>(x);
    k_main<<<dim3(NOUT / BN, BATCH / BM), THREADS, SMEM_BYTES>>>(b, out);
}

// round 11
// speedup vs baseline: 1.1748x; 1.0335x over previous
#include <cuda_runtime.h>
#include <cuda_fp16.h>
#include <stdint.h>

#define BATCH 16384
#define NIN   128
#define NFEAT 8384
#define NOUT  512

#define BM 128
#define BN 128
#define BK 64
#define NCHUNK (NFEAT / BK)   // 131
#define THREADS 128
#define NSTAGE 3

// ---- global scratch (static __device__, no allocs) ----
__device__ __align__(16) __half g_A[(size_t)BATCH * NFEAT];    // expanded features fp16 (274.7MB)
__device__ __align__(16) __half g_Wt[(size_t)NOUT * NFEAT];    // W^T fp16 [n][k]
__device__ __align__(16) unsigned short g_tab[NFEAT];          // i | (j<<8); j=128 => linear

// ===================== prep kernels =====================

// transpose W [8384,512] f32 -> Wt [512,8384] fp16; blocks with y==0 also fill g_tab
__global__ void k_wt(const float* __restrict__ W) {
    __shared__ float sm[64][65];
    int k0 = blockIdx.x * 64, n0 = blockIdx.y * 64;
    int tid = threadIdx.x;

    if (blockIdx.y == 0 && tid < 64) {             // f = k0 + tid covers 131*64 = 8384
        int f = k0 + tid;
        int i, j;
        if (f < NIN) { i = f; j = NIN; }
        else {
            int t = f - NIN;
            i = 0;
            while (NIN * (i + 1) - (i + 1) * i / 2 <= t) i++;
            j = i + (t - (NIN * i - i * (i - 1) / 2));
        }
        g_tab[f] = (unsigned short)(i | (j << 8));
    }

    for (int idx = tid; idx < 64 * 64; idx += 256) {
        int r = idx >> 6, c = idx & 63;           // r: k-local, c: n-local
        sm[c][r] = W[(size_t)(k0 + r) * NOUT + n0 + c];
    }
    __syncthreads();
    for (int idx = tid; idx < 64 * 32; idx += 256) {
        int nl = idx >> 5, kl = (idx & 31) * 2;
        float v0 = sm[nl][kl], v1 = sm[nl][kl + 1];
        uint32_t h;
        asm("cvt.rn.f16x2.f32 %0, %1, %2;" : "=r"(h) : "f"(v1), "f"(v0));
        size_t o = (size_t)(n0 + nl) * NFEAT + k0 + kl;   // even
        *(uint32_t*)((unsigned short*)g_Wt + o) = h;
    }
}

// expand X -> fp16 feature matrix [BATCH][NFEAT]  (R7-proven table-driven form)
__global__ void __launch_bounds__(256, 4) k_expand(const float* __restrict__ X) {
    __shared__ float xs[129];
    const int b = blockIdx.x;
    const int tid = threadIdx.x;
    if (tid < 128) xs[tid] = X[(size_t)b * NIN + tid];
    if (tid == 0) xs[128] = 1.0f;
    __syncthreads();

    __half* A = g_A + (size_t)b * NFEAT;
    #pragma unroll 1
    for (int g = tid; g < NFEAT / 8; g += 256) {       // 1048 groups of 8 feats
        uint4 tv = *(const uint4*)&g_tab[g * 8];
        uint32_t tw[4] = {tv.x, tv.y, tv.z, tv.w};
        uint4 HP;
        uint32_t* hp = (uint32_t*)&HP;
        #pragma unroll
        for (int q = 0; q < 4; ++q) {
            uint32_t wv = tw[q];
            int i0 = wv & 255, j0 = (wv >> 8) & 255;
            int i1 = (wv >> 16) & 255, j1 = (wv >> 24) & 255;
            float v0 = xs[i0] * xs[j0];
            float v1 = xs[i1] * xs[j1];
            uint32_t h;
            asm("cvt.rn.f16x2.f32 %0, %1, %2;" : "=r"(h) : "f"(v1), "f"(v0));
            hp[q] = h;
        }
        *(uint4*)(A + g * 8) = HP;
    }
}

// ===================== PTX helpers =====================

__device__ __forceinline__ uint32_t smem_u32(const void* p) {
    uint32_t a;
    asm("{ .reg .u64 t; cvta.to.shared.u64 t, %1; cvt.u32.u64 %0, t; }" : "=r"(a) : "l"(p));
    return a;
}

__device__ __forceinline__ void ldsm4(uint32_t* r, uint32_t addr) {
    asm volatile("ldmatrix.sync.aligned.m8n8.x4.shared.b16 {%0,%1,%2,%3}, [%4];"
                 : "=r"(r[0]), "=r"(r[1]), "=r"(r[2]), "=r"(r[3]) : "r"(addr));
}

__device__ __forceinline__ void mma_f16(float* d, const uint32_t* a, const uint32_t* b) {
    asm volatile(
        "mma.sync.aligned.m16n8k16.row.col.f32.f16.f16.f32 "
        "{%0,%1,%2,%3}, {%4,%5,%6,%7}, {%8,%9}, {%0,%1,%2,%3};"
        : "+f"(d[0]), "+f"(d[1]), "+f"(d[2]), "+f"(d[3])
        : "r"(a[0]), "r"(a[1]), "r"(a[2]), "r"(a[3]), "r"(b[0]), "r"(b[1]));
}

__device__ __forceinline__ void cp16(uint32_t dst, const void* src) {
    asm volatile("cp.async.cg.shared.global [%0], [%1], 16;" :: "r"(dst), "l"(src) : "memory");
}

// ===================== main GEMM kernel (R7 — proven 341us) =====================
// 4 warps, each owning a 64x64 output tile; cross-chunk register pipelining:
// every chunk is entered with its ks0 fragments already loaded (no ldsm bubble).
// SMEM per stage (32768 B): A 128x64 fp16 (16K) | B (+16384)
// Rows are 128B with SW128 XOR swizzle: chunk' = chunk ^ (row & 7)
#define STAGE_B 32768
#define SMEM_BYTES (NSTAGE * STAGE_B)   // 98304 -> 2 CTAs/SM

__global__ void __launch_bounds__(THREADS, 2)
k_main(const float* __restrict__ bias, float* __restrict__ out) {
    extern __shared__ char sm[];
    const uint32_t sb = smem_u32(sm);
    const int tid = threadIdx.x;
    const int lane = tid & 31;
    const int wid = tid >> 5;
    const int warp_m = wid & 1;       // 2 warps along M (64 rows each)
    const int warp_n = wid >> 1;      // 2 warps along N (64 cols each)
    const int n0 = blockIdx.x * BN;
    const int m0 = blockIdx.y * BM;

    float acc[4][8][4];
    #pragma unroll
    for (int a = 0; a < 4; ++a)
        #pragma unroll
        for (int b = 0; b < 8; ++b)
            #pragma unroll
            for (int c = 0; c < 4; ++c) acc[a][b][c] = 0.0f;

    // ---- cp.async staging: 1024 16B chunks each for A and B, 128 threads ----
    auto load_stage = [&](int s, int c) {
        const uint32_t base = sb + (uint32_t)(s * STAGE_B);
        const size_t koff = (size_t)c * BK;
        #pragma unroll
        for (int i = 0; i < 8; ++i) {
            int g = tid + i * 128;
            int r = g >> 3, ch = g & 7;
            uint32_t doff = (uint32_t)(r * 128 + (((ch ^ (r & 7))) << 4));
            cp16(base + doff,         g_A  + (size_t)(m0 + r) * NFEAT + koff + ch * 8);
            cp16(base + 16384 + doff, g_Wt + (size_t)(n0 + r) * NFEAT + koff + ch * 8);
        }
    };

    // ldmatrix per-lane constants
    const uint32_t sel = (uint32_t)(lane & 7);
    const uint32_t a_rowoff = (uint32_t)((warp_m * 64 + (lane & 15)) * 128);
    const uint32_t a_ch = (uint32_t)(lane >> 4);
    const uint32_t b_rowoff = (uint32_t)((warp_n * 64 + ((lane >> 4) << 3) + (lane & 7)) * 128);
    const uint32_t b_ch = (uint32_t)((lane >> 3) & 1);

    uint32_t Af[2][4][4], Bf[2][4][4];   // register double buffer

    auto load_frags = [&](uint32_t base, int ks, int buf) {
        const uint32_t ach = (((uint32_t)(ks * 2) + a_ch) ^ sel) << 4;
        const uint32_t bch = (((uint32_t)(ks * 2) + b_ch) ^ sel) << 4;
        #pragma unroll
        for (int mt = 0; mt < 4; ++mt)
            ldsm4(Af[buf][mt], base + a_rowoff + (uint32_t)(mt * 16 * 128) + ach);
        #pragma unroll
        for (int np = 0; np < 4; ++np)
            ldsm4(Bf[buf][np], base + 16384 + b_rowoff + (uint32_t)(np * 16 * 128) + bch);
    };

    auto mma_step = [&](int buf) {
        #pragma unroll
        for (int mt = 0; mt < 4; ++mt)
            #pragma unroll
            for (int np = 0; np < 4; ++np)
                #pragma unroll
                for (int h2 = 0; h2 < 2; ++h2)
                    mma_f16(acc[mt][np * 2 + h2], Af[buf][mt], &Bf[buf][np][h2 * 2]);
    };

    // ---- prologue ----
    load_stage(0, 0);
    asm volatile("cp.async.commit_group;" ::: "memory");
    load_stage(1, 1);
    asm volatile("cp.async.commit_group;" ::: "memory");
    asm volatile("cp.async.wait_group 1;" ::: "memory");  // G0 done -> stage 0 ready
    __syncthreads();
    load_frags(sb, 0, 0);                                 // chunk 0 ks0 -> buf0

    // ---- mainloop: barrier at tail; every chunk enters with ks0 in buf0 ----
    #pragma unroll 1
    for (int c = 0; c < NCHUNK; ++c) {
        if (c + 2 < NCHUNK) load_stage((c + 2) % 3, c + 2);
        asm volatile("cp.async.commit_group;" ::: "memory");  // empty commit near end keeps FIFO math valid
        const uint32_t base = sb + (uint32_t)((c % 3) * STAGE_B);
        load_frags(base, 1, 1); mma_step(0);
        load_frags(base, 2, 0); mma_step(1);
        load_frags(base, 3, 1); mma_step(0);
        // tail: ensure stage c+1 arrived (wait_group 1 -> G(c+1) retired) and visible
        asm volatile("cp.async.wait_group 1;" ::: "memory");
        __syncthreads();
        if (c + 1 < NCHUNK)
            load_frags(sb + (uint32_t)(((c + 1) % 3) * STAGE_B), 0, 0);  // next chunk ks0
        mma_step(1);                                       // hides the prefetch latency
    }

    // ---- epilogue ----
    const int gid = lane >> 2, tig = lane & 3;
    #pragma unroll
    for (int mt = 0; mt < 4; ++mt) {
        #pragma unroll
        for (int nt = 0; nt < 8; ++nt) {
            int row = m0 + warp_m * 64 + mt * 16 + gid;
            int col = n0 + warp_n * 64 + nt * 8 + tig * 2;
            float b0 = bias[col], b1 = bias[col + 1];
            float2 v0 = {acc[mt][nt][0] + b0, acc[mt][nt][1] + b1};
            float2 v1 = {acc[mt][nt][2] + b0, acc[mt][nt][3] + b1};
            *(float2*)(out + (size_t)row * NOUT + col) = v0;
            *(float2*)(out + (size_t)(row + 8) * NOUT + col) = v1;
        }
    }
}

// ===================== launcher =====================

extern "C" void kernel_launch(void* const* d_in, const int* in_sizes, int n_in,
                              void* d_out, int out_size) {
    const float* x = (const float*)d_in[0];
    const float* w = (const float*)d_in[1];
    const float* b = (const float*)d_in[2];
    float* out = (float*)d_out;

    cudaFuncSetAttribute(k_main, cudaFuncAttributeMaxDynamicSharedMemorySize, SMEM_BYTES);

    k_wt<<<dim3(NFEAT / 64, NOUT / 64), 256>>>(w);
    k_expand<<<BATCH, 256>>>(x);
    k_main<<<dim3(NOUT / BN, BATCH / BM), THREADS, SMEM_BYTES>>>(b, out);
}

// round 12
// speedup vs baseline: 1.2242x; 1.0421x over previous
#include <cuda_runtime.h>
#include <cuda_fp16.h>
#include <stdint.h>

#define BATCH 16384
#define NIN   128
#define NFEAT 8384
#define NOUT  512

#define BM 128
#define BN 128
#define BK 64
#define NCHUNK (NFEAT / BK)   // 131
#define THREADS 128
#define NSTAGE 3

#define WT_BLOCKS 1048        // 131 x 8 transpose tiles
#define NGRP (NFEAT / 8)      // 1048 expand groups per row

// ---- global scratch (static __device__, no allocs) ----
__device__ __align__(16) __half g_A[(size_t)BATCH * NFEAT];    // expanded features fp16 (274.7MB)
__device__ __align__(16) __half g_Wt[(size_t)NOUT * NFEAT];    // W^T fp16 [n][k]

// ===================== fused prep kernel =====================
// Blocks [0, 1048): transpose W [8384,512] f32 -> Wt [512,8384] fp16.
// Blocks [1048, 1048+16384): expand one batch row -> fp16 features, with
// inline (i,j) index math (closed form + exact fixup) -- no table, no dependency.
__global__ void __launch_bounds__(256) k_prep(const float* __restrict__ W,
                                              const float* __restrict__ X) {
    __shared__ float shbuf[64 * 65];
    const int tid = threadIdx.x;

    if (blockIdx.x < WT_BLOCKS) {
        // ---- transpose tile ----
        const int kb = blockIdx.x;
        const int k0 = (kb % 131) * 64, n0 = (kb / 131) * 64;
        for (int idx = tid; idx < 64 * 64; idx += 256) {
            int r = idx >> 6, c = idx & 63;           // r: k-local, c: n-local
            shbuf[c * 65 + r] = W[(size_t)(k0 + r) * NOUT + n0 + c];
        }
        __syncthreads();
        for (int idx = tid; idx < 64 * 32; idx += 256) {
            int nl = idx >> 5, kl = (idx & 31) * 2;
            float v0 = shbuf[nl * 65 + kl], v1 = shbuf[nl * 65 + kl + 1];
            uint32_t h;
            asm("cvt.rn.f16x2.f32 %0, %1, %2;" : "=r"(h) : "f"(v1), "f"(v0));
            size_t o = (size_t)(n0 + nl) * NFEAT + k0 + kl;   // even
            *(uint32_t*)((unsigned short*)g_Wt + o) = h;
        }
        return;
    }

    // ---- expand one batch row ----
    const int b = blockIdx.x - WT_BLOCKS;
    float* xs = shbuf;                                  // 128 floats
    if (tid < 128) xs[tid] = X[(size_t)b * NIN + tid];
    __syncthreads();

    __half* A = g_A + (size_t)b * NFEAT;
    #pragma unroll 1
    for (int g = tid; g < NGRP; g += 256) {             // 8 features per group
        uint4 HP;
        uint32_t* hp = (uint32_t*)&HP;
        if (g < 16) {                                   // linear features (f < 128)
            const int f0 = g * 8;
            #pragma unroll
            for (int q = 0; q < 4; ++q) {
                float v0 = xs[f0 + 2 * q] * 1.0f;
                float v1 = xs[f0 + 2 * q + 1] * 1.0f;
                asm("cvt.rn.f16x2.f32 %0, %1, %2;" : "=r"(hp[q]) : "f"(v1), "f"(v0));
            }
        } else {                                        // quadratic: f = 8g, t = f-128
            const int t = 8 * g - 128;
            // i = largest row with T(i) <= t, T(i) = i*(257-i)/2
            float s = sqrtf((float)(66049 - 8 * t));
            int i = (int)((257.0f - s) * 0.5f);
            if (i < 0) i = 0;
            if (i > 127) i = 127;
            while (i < 127 && (i + 1) * (257 - (i + 1)) / 2 <= t) ++i;   // fixup up
            while (i > 0 && i * (257 - i) / 2 > t) --i;                  // fixup down
            int j = i + (t - i * (257 - i) / 2);
            float vals[8];
            #pragma unroll
            for (int q = 0; q < 8; ++q) {
                vals[q] = xs[i] * xs[j];
                ++j;
                if (j == 128) { ++i; j = i; }
            }
            #pragma unroll
            for (int q = 0; q < 4; ++q)
                asm("cvt.rn.f16x2.f32 %0, %1, %2;"
                    : "=r"(hp[q]) : "f"(vals[2 * q + 1]), "f"(vals[2 * q]));
        }
        *(uint4*)(A + g * 8) = HP;
    }
}

// ===================== PTX helpers =====================

__device__ __forceinline__ uint32_t smem_u32(const void* p) {
    uint32_t a;
    asm("{ .reg .u64 t; cvta.to.shared.u64 t, %1; cvt.u32.u64 %0, t; }" : "=r"(a) : "l"(p));
    return a;
}

__device__ __forceinline__ void ldsm4(uint32_t* r, uint32_t addr) {
    asm volatile("ldmatrix.sync.aligned.m8n8.x4.shared.b16 {%0,%1,%2,%3}, [%4];"
                 : "=r"(r[0]), "=r"(r[1]), "=r"(r[2]), "=r"(r[3]) : "r"(addr));
}

__device__ __forceinline__ void mma_f16(float* d, const uint32_t* a, const uint32_t* b) {
    asm volatile(
        "mma.sync.aligned.m16n8k16.row.col.f32.f16.f16.f32 "
        "{%0,%1,%2,%3}, {%4,%5,%6,%7}, {%8,%9}, {%0,%1,%2,%3};"
        : "+f"(d[0]), "+f"(d[1]), "+f"(d[2]), "+f"(d[3])
        : "r"(a[0]), "r"(a[1]), "r"(a[2]), "r"(a[3]), "r"(b[0]), "r"(b[1]));
}

__device__ __forceinline__ void cp16(uint32_t dst, const void* src) {
    asm volatile("cp.async.cg.shared.global [%0], [%1], 16;" :: "r"(dst), "l"(src) : "memory");
}

// ===================== main GEMM kernel (R7 — proven 341us) =====================
// 4 warps, each owning a 64x64 output tile; cross-chunk register pipelining:
// every chunk is entered with its ks0 fragments already loaded (no ldsm bubble).
// SMEM per stage (32768 B): A 128x64 fp16 (16K) | B (+16384)
// Rows are 128B with SW128 XOR swizzle: chunk' = chunk ^ (row & 7)
#define STAGE_B 32768
#define SMEM_BYTES (NSTAGE * STAGE_B)   // 98304 -> 2 CTAs/SM

__global__ void __launch_bounds__(THREADS, 2)
k_main(const float* __restrict__ bias, float* __restrict__ out) {
    extern __shared__ char sm[];
    const uint32_t sb = smem_u32(sm);
    const int tid = threadIdx.x;
    const int lane = tid & 31;
    const int wid = tid >> 5;
    const int warp_m = wid & 1;       // 2 warps along M (64 rows each)
    const int warp_n = wid >> 1;      // 2 warps along N (64 cols each)
    const int n0 = blockIdx.x * BN;
    const int m0 = blockIdx.y * BM;

    float acc[4][8][4];
    #pragma unroll
    for (int a = 0; a < 4; ++a)
        #pragma unroll
        for (int b = 0; b < 8; ++b)
            #pragma unroll
            for (int c = 0; c < 4; ++c) acc[a][b][c] = 0.0f;

    // ---- cp.async staging: 1024 16B chunks each for A and B, 128 threads ----
    auto load_stage = [&](int s, int c) {
        const uint32_t base = sb + (uint32_t)(s * STAGE_B);
        const size_t koff = (size_t)c * BK;
        #pragma unroll
        for (int i = 0; i < 8; ++i) {
            int g = tid + i * 128;
            int r = g >> 3, ch = g & 7;
            uint32_t doff = (uint32_t)(r * 128 + (((ch ^ (r & 7))) << 4));
            cp16(base + doff,         g_A  + (size_t)(m0 + r) * NFEAT + koff + ch * 8);
            cp16(base + 16384 + doff, g_Wt + (size_t)(n0 + r) * NFEAT + koff + ch * 8);
        }
    };

    // ldmatrix per-lane constants
    const uint32_t sel = (uint32_t)(lane & 7);
    const uint32_t a_rowoff = (uint32_t)((warp_m * 64 + (lane & 15)) * 128);
    const uint32_t a_ch = (uint32_t)(lane >> 4);
    const uint32_t b_rowoff = (uint32_t)((warp_n * 64 + ((lane >> 4) << 3) + (lane & 7)) * 128);
    const uint32_t b_ch = (uint32_t)((lane >> 3) & 1);

    uint32_t Af[2][4][4], Bf[2][4][4];   // register double buffer

    auto load_frags = [&](uint32_t base, int ks, int buf) {
        const uint32_t ach = (((uint32_t)(ks * 2) + a_ch) ^ sel) << 4;
        const uint32_t bch = (((uint32_t)(ks * 2) + b_ch) ^ sel) << 4;
        #pragma unroll
        for (int mt = 0; mt < 4; ++mt)
            ldsm4(Af[buf][mt], base + a_rowoff + (uint32_t)(mt * 16 * 128) + ach);
        #pragma unroll
        for (int np = 0; np < 4; ++np)
            ldsm4(Bf[buf][np], base + 16384 + b_rowoff + (uint32_t)(np * 16 * 128) + bch);
    };

    auto mma_step = [&](int buf) {
        #pragma unroll
        for (int mt = 0; mt < 4; ++mt)
            #pragma unroll
            for (int np = 0; np < 4; ++np)
                #pragma unroll
                for (int h2 = 0; h2 < 2; ++h2)
                    mma_f16(acc[mt][np * 2 + h2], Af[buf][mt], &Bf[buf][np][h2 * 2]);
    };

    // ---- prologue ----
    load_stage(0, 0);
    asm volatile("cp.async.commit_group;" ::: "memory");
    load_stage(1, 1);
    asm volatile("cp.async.commit_group;" ::: "memory");
    asm volatile("cp.async.wait_group 1;" ::: "memory");  // G0 done -> stage 0 ready
    __syncthreads();
    load_frags(sb, 0, 0);                                 // chunk 0 ks0 -> buf0

    // ---- mainloop: barrier at tail; every chunk enters with ks0 in buf0 ----
    #pragma unroll 1
    for (int c = 0; c < NCHUNK; ++c) {
        if (c + 2 < NCHUNK) load_stage((c + 2) % 3, c + 2);
        asm volatile("cp.async.commit_group;" ::: "memory");  // empty commit near end keeps FIFO math valid
        const uint32_t base = sb + (uint32_t)((c % 3) * STAGE_B);
        load_frags(base, 1, 1); mma_step(0);
        load_frags(base, 2, 0); mma_step(1);
        load_frags(base, 3, 1); mma_step(0);
        // tail: ensure stage c+1 arrived (wait_group 1 -> G(c+1) retired) and visible
        asm volatile("cp.async.wait_group 1;" ::: "memory");
        __syncthreads();
        if (c + 1 < NCHUNK)
            load_frags(sb + (uint32_t)(((c + 1) % 3) * STAGE_B), 0, 0);  // next chunk ks0
        mma_step(1);                                       // hides the prefetch latency
    }

    // ---- epilogue ----
    const int gid = lane >> 2, tig = lane & 3;
    #pragma unroll
    for (int mt = 0; mt < 4; ++mt) {
        #pragma unroll
        for (int nt = 0; nt < 8; ++nt) {
            int row = m0 + warp_m * 64 + mt * 16 + gid;
            int col = n0 + warp_n * 64 + nt * 8 + tig * 2;
            float b0 = bias[col], b1 = bias[col + 1];
            float2 v0 = {acc[mt][nt][0] + b0, acc[mt][nt][1] + b1};
            float2 v1 = {acc[mt][nt][2] + b0, acc[mt][nt][3] + b1};
            *(float2*)(out + (size_t)row * NOUT + col) = v0;
            *(float2*)(out + (size_t)(row + 8) * NOUT + col) = v1;
        }
    }
}

// ===================== launcher =====================

extern "C" void kernel_launch(void* const* d_in, const int* in_sizes, int n_in,
                              void* d_out, int out_size) {
    const float* x = (const float*)d_in[0];
    const float* w = (const float*)d_in[1];
    const float* b = (const float*)d_in[2];
    float* out = (float*)d_out;

    cudaFuncSetAttribute(k_main, cudaFuncAttributeMaxDynamicSharedMemorySize, SMEM_BYTES);

    k_prep<<<WT_BLOCKS + BATCH, 256>>>(w, x);
    k_main<<<dim3(NOUT / BN, BATCH / BM), THREADS, SMEM_BYTES>>>(b, out);
}